// round 8
// baseline (speedup 1.0000x reference)
#include <cuda_runtime.h>
#include <cuda_bf16.h>
#include <cstdint>
#include <cstddef>

// Shapes: user [B=32, U=128, D=256] fp32, image [B=32, I=256, D=256] fp32
// out = concat(user * img_sum[b,1,:], image * user_sum[b,1,:])
//
// cp.async double-buffered pipeline: each CTA handles TWO (b, d-chunk) items.
// All loads for both items are issued up front via cp.async (no payload regs,
// no load-wait on the second item); item B's in-flight loads hide item A's
// reduce + store phase. Traffic stays at the 24MB minimum.

#define BB 32
#define UU 128
#define II 256
#define DD 256

#define DCH 16               // floats per item d-chunk
#define NCH (DD / DCH)       // 16
#define NITEMS (BB * NCH)    // 512
#define NT 256
#define GRID (NITEMS / 2)    // 256 CTAs, 2 items each
#define NWARPS (NT / 32)     // 8
#define TX 4                 // float4 lanes per row (64B contiguous)

__device__ __forceinline__ float4 f4add(float4 a, float4 b) {
    return make_float4(a.x + b.x, a.y + b.y, a.z + b.z, a.w + b.w);
}
__device__ __forceinline__ float4 f4mul(float4 a, float4 b) {
    return make_float4(a.x * b.x, a.y * b.y, a.z * b.z, a.w * b.w);
}
__device__ __forceinline__ void f4shfl_acc(float4& a, int m) {
    a.x += __shfl_xor_sync(0xffffffffu, a.x, m);
    a.y += __shfl_xor_sync(0xffffffffu, a.y, m);
    a.z += __shfl_xor_sync(0xffffffffu, a.z, m);
    a.w += __shfl_xor_sync(0xffffffffu, a.w, m);
}
__device__ __forceinline__ void cp16(uint32_t dst, const void* src) {
    asm volatile("cp.async.cg.shared.global [%0], [%1], 16;" :: "r"(dst), "l"(src));
}

__global__ __launch_bounds__(NT)
void ExternalInteraction_65609920413984_kernel(
    const float* __restrict__ user,
    const float* __restrict__ img,
    float* __restrict__ out_user,
    float* __restrict__ out_img)
{
    __shared__ float uS[2][UU * DCH];        // 16 KB
    __shared__ float iS[2][II * DCH];        // 32 KB
    __shared__ float4 wsI[2][NWARPS][TX];
    __shared__ float4 wsU[2][NWARPS][TX];

    const int tx   = threadIdx.x & (TX - 1);  // 0..3
    const int ty   = threadIdx.x >> 2;        // 0..63
    const int warp = threadIdx.x >> 5;
    const int lane = threadIdx.x & 31;

    const int items[2] = { (int)blockIdx.x, (int)blockIdx.x + GRID };

    // ---- Issue ALL cp.async loads for both items up front ----
    #pragma unroll
    for (int p = 0; p < 2; p++) {
        const int it = items[p];
        const int b  = it >> 4;
        const int d0 = (it & (NCH - 1)) * DCH;
        const float* ub = user + (size_t)b * UU * DD + d0 + tx * 4;
        const float* ib = img  + (size_t)b * II * DD + d0 + tx * 4;
        uint32_t ud = (uint32_t)__cvta_generic_to_shared(&uS[p][tx * 4]);
        uint32_t id = (uint32_t)__cvta_generic_to_shared(&iS[p][tx * 4]);
        #pragma unroll
        for (int k = 0; k < UU / 64; k++) {   // 2 user rows
            int r = ty + 64 * k;
            cp16(ud + r * DCH * 4, ub + (size_t)r * DD);
        }
        #pragma unroll
        for (int k = 0; k < II / 64; k++) {   // 4 image rows
            int r = ty + 64 * k;
            cp16(id + r * DCH * 4, ib + (size_t)r * DD);
        }
        asm volatile("cp.async.commit_group;");
    }

    // ---- Process the two items; B's loads land under A's compute/stores ----
    #pragma unroll
    for (int p = 0; p < 2; p++) {
        if (p == 0) asm volatile("cp.async.wait_group 1;");
        else        asm volatile("cp.async.wait_group 0;");

        const int it = items[p];
        const int b  = it >> 4;
        const int d0 = (it & (NCH - 1)) * DCH;

        // Pull this thread's rows from smem into registers (it wrote them)
        float4 uv[2], iv[4];
        #pragma unroll
        for (int k = 0; k < 2; k++)
            uv[k] = *reinterpret_cast<const float4*>(&uS[p][(ty + 64 * k) * DCH + tx * 4]);
        #pragma unroll
        for (int k = 0; k < 4; k++)
            iv[k] = *reinterpret_cast<const float4*>(&iS[p][(ty + 64 * k) * DCH + tx * 4]);

        // Column sums: intra-warp shuffle tree over ty bits (lane bits 2,3,4)
        float4 ai = f4add(f4add(iv[0], iv[1]), f4add(iv[2], iv[3]));
        float4 au = f4add(uv[0], uv[1]);
        f4shfl_acc(ai, 4);  f4shfl_acc(ai, 8);  f4shfl_acc(ai, 16);
        f4shfl_acc(au, 4);  f4shfl_acc(au, 8);  f4shfl_acc(au, 16);

        if (lane < TX) { wsI[p][warp][tx] = ai; wsU[p][warp][tx] = au; }
        __syncthreads();                       // one barrier per item

        float4 is = wsI[p][0][tx];
        float4 us = wsU[p][0][tx];
        #pragma unroll
        for (int w = 1; w < NWARPS; w++) {
            is = f4add(is, wsI[p][w][tx]);
            us = f4add(us, wsU[p][w][tx]);
        }

        // Stores straight from registers
        float* oub = out_user + (size_t)b * UU * DD + d0 + tx * 4;
        float* oib = out_img  + (size_t)b * II * DD + d0 + tx * 4;
        #pragma unroll
        for (int k = 0; k < 2; k++)
            *reinterpret_cast<float4*>(oub + (size_t)(ty + 64 * k) * DD) = f4mul(uv[k], is);
        #pragma unroll
        for (int k = 0; k < 4; k++)
            *reinterpret_cast<float4*>(oib + (size_t)(ty + 64 * k) * DD) = f4mul(iv[k], us);
    }
}

extern "C" void kernel_launch(void* const* d_in, const int* in_sizes, int n_in,
                              void* d_out, int out_size)
{
    (void)in_sizes; (void)n_in; (void)out_size;
    const float* user = (const float*)d_in[0];
    const float* img  = (const float*)d_in[1];
    float* out_user = (float*)d_out;
    float* out_img  = (float*)d_out + (size_t)BB * UU * DD;

    ExternalInteraction_65609920413984_kernel
        <<<GRID, NT>>>(user, img, out_user, out_img);
}